// round 3
// baseline (speedup 1.0000x reference)
#include <cuda_runtime.h>

// Problem constants
#define P_GAIN     2.0f
#define P_BASELINE 100.0f
static constexpr int B = 32;
static constexpr int E = 64;
static constexpr int H = 128;
static constexpr int W = 128;
static constexpr int R = 13;     // ROI size
static constexpr int D = 32;     // z slices
static constexpr int HALF = R / 2;
static constexpr int PIX = H * W;          // 16384 pixels per image
static constexpr int VEC_ITERS = PIX / 4;  // 4096 float4 per image

// ---------------------------------------------------------------------------
// One block per (frame, emitter) output image [H,W].
// Phase 1: threads 0..168 evaluate the tricubic-spline PSF patch (13x13),
//          pre-scaled by GAIN * n_photons, into shared memory.
// Phase 2: all 256 threads stream the image with float4 stores:
//          out = bg*GAIN + BASELINE (+ patch inside the ROI).
//
// Index semantics (matching JAX .at[].add(..., mode='drop')):
//   negative target indices WRAP (idx += H or W), indices >= H/W are DROPPED.
// For pixel row `row`, patch row rr = row - r0 is valid if rr in [0,R);
// the wrapped alias is rr in [128, 128+R) (target r0+rr' < 0 wrapped by +128),
// handled by `if (rr >= 128) rr -= 128;`. Same for columns.
// ---------------------------------------------------------------------------
__global__ __launch_bounds__(256) void render_kernel(const float* __restrict__ xyz,
                                                     const float* __restrict__ nph,
                                                     const float* __restrict__ bg,
                                                     const float* __restrict__ coeff,
                                                     float* __restrict__ out)
{
    const int e     = blockIdx.x;   // 0 .. B*E-1
    const int frame = e >> 6;       // e / E (E == 64)

    __shared__ float s_patch[R * R];

    // ---- per-emitter setup, computed redundantly (broadcast loads) ----
    const float x = xyz[e * 3 + 0];
    const float y = xyz[e * 3 + 1];
    const float z = xyz[e * 3 + 2];

    const float xf = floorf(x);
    const float yf = floorf(y);
    const float dx = x - xf;
    const float dy = y - yf;

    float zc = fminf(fmaxf(z, 0.0f), (float)(D - 1) - 1e-6f);
    const float zf = floorf(zc);
    const int   zi = (int)zf;
    const float dz = zc - zf;

    const int r0 = (int)yf - HALF;   // top row of ROI in image coords
    const int c0 = (int)xf - HALF;   // left col of ROI

    const int t = threadIdx.x;

    // ---- phase 1: patch evaluation ----
    if (t < R * R) {
        const float px1 = dx, px2 = dx * dx, px3 = px2 * dx;
        const float py1 = dy, py2 = dy * dy, py3 = py2 * dy;
        const float pz1 = dz, pz2 = dz * dz, pz3 = pz2 * dz;
        const float amp = nph[e] * P_GAIN;

        const int r = t / R;
        const int c = t - r * R;
        // coeff layout: [D][R][R][4(z)][4(y)][4(x)], x innermost.
        const float4* __restrict__ base4 =
            reinterpret_cast<const float4*>(coeff + (((size_t)zi * R + r) * R + c) * 64);

        float sum = 0.0f;
        #pragma unroll
        for (int a = 0; a < 4; ++a) {
            const float pza = (a == 0) ? 1.0f : (a == 1) ? pz1 : (a == 2) ? pz2 : pz3;
            float sb = 0.0f;
            #pragma unroll
            for (int b = 0; b < 4; ++b) {
                const float pyb = (b == 0) ? 1.0f : (b == 1) ? py1 : (b == 2) ? py2 : py3;
                const float4 f = base4[a * 4 + b];
                float sc = f.x;
                sc = fmaf(f.y, px1, sc);
                sc = fmaf(f.z, px2, sc);
                sc = fmaf(f.w, px3, sc);
                sb = fmaf(sc, pyb, sb);
            }
            sum = fmaf(sb, pza, sum);
        }
        s_patch[t] = sum * amp;
    }
    __syncthreads();

    // ---- phase 2: stream the image ----
    const float4* __restrict__ bg4  = reinterpret_cast<const float4*>(bg + (size_t)frame * PIX);
    float4* __restrict__       out4 = reinterpret_cast<float4*>(out + (size_t)e * PIX);

    #pragma unroll
    for (int it = 0; it < VEC_ITERS / 256; ++it) {
        const int i   = it * 256 + t;            // float4 index within image
        const int pix = i << 2;
        const int row = pix >> 7;                // W == 128
        const int col = pix & (W - 1);

        const float4 b4 = bg4[i];
        float4 v;
        v.x = fmaf(b4.x, P_GAIN, P_BASELINE);
        v.y = fmaf(b4.y, P_GAIN, P_BASELINE);
        v.z = fmaf(b4.z, P_GAIN, P_BASELINE);
        v.w = fmaf(b4.w, P_GAIN, P_BASELINE);

        int rr = row - r0;                       // in [-127, 133]
        if (rr >= H) rr -= H;                    // wrapped negative target
        if ((unsigned)rr < (unsigned)R) {
            const int cc = col - c0;             // patch column of v.x
            float* vp = &v.x;
            #pragma unroll
            for (int j = 0; j < 4; ++j) {
                int cj = cc + j;
                if (cj >= W) cj -= W;            // wrapped negative target
                if ((unsigned)cj < (unsigned)R) vp[j] += s_patch[rr * R + cj];
            }
        }
        out4[i] = v;
    }
}

// ---------------------------------------------------------------------------
// Launch. Inputs identified by element count (robust to metadata ordering):
//   xyz [B,E,3]=6144, n_photons [B,E]=2048, bg [B,H,W]=524288,
//   coeff [D,R,R,4,4,4]=346112.  Output: [B,E,H,W] f32 = 33554432.
// ---------------------------------------------------------------------------
extern "C" void kernel_launch(void* const* d_in, const int* in_sizes, int n_in,
                              void* d_out, int out_size)
{
    const float* xyz   = nullptr;
    const float* nph   = nullptr;
    const float* bg    = nullptr;
    const float* coeff = nullptr;
    for (int i = 0; i < n_in; ++i) {
        switch (in_sizes[i]) {
            case B * E * 3:           xyz   = (const float*)d_in[i]; break;
            case B * E:               nph   = (const float*)d_in[i]; break;
            case B * H * W:           bg    = (const float*)d_in[i]; break;
            case D * R * R * 64:      coeff = (const float*)d_in[i]; break;
        }
    }
    float* out = (float*)d_out;

    render_kernel<<<B * E, 256>>>(xyz, nph, bg, coeff, out);
}